// round 9
// baseline (speedup 1.0000x reference)
#include <cuda_runtime.h>
#include <cstdint>

#define BB     8
#define NPTS   8192
#define GRIDD  32
#define CELLS  (GRIDD * GRIDD * GRIDD)
#define RANGE_LO (-6.5f)
#define S_CELL   0.40625f          // 13.0 / 32
#define INV_S    (1.0f / S_CELL)

// ---- scratch (no allocations allowed) ----
__device__ float4   g_sorted[2][BB][NPTS];   // cell-sorted points (x,y,z,0)
__device__ unsigned g_cnt[2][BB][CELLS];     // per-cell counts
__device__ unsigned g_cs[2][BB][CELLS];      // packed: start | (cnt << 16)
__device__ unsigned g_fill[2][BB][CELLS];    // scatter cursors
__device__ double   g_loss[2];

__device__ __forceinline__ int cell_coord(float v) {
    int c = (int)floorf((v - RANGE_LO) * INV_S);
    return min(max(c, 0), GRIDD - 1);
}

// ---- zero counters/cursors/accumulators ----
__global__ void zero_kernel() {
    int i = blockIdx.x * blockDim.x + threadIdx.x;
    if (i < 2 * BB * CELLS) {
        ((unsigned*)g_cnt)[i] = 0u;
        ((unsigned*)g_fill)[i] = 0u;
    }
    if (i < 2) g_loss[i] = 0.0;
}

// ---- histogram: count points per cell ----
__global__ void hist_kernel(const float* __restrict__ pred, const float* __restrict__ targ) {
    int i = blockIdx.x * blockDim.x + threadIdx.x;
    if (i >= 2 * BB * NPTS) return;
    int cloud = i / (BB * NPTS);
    int rem = i - cloud * (BB * NPTS);
    const float* src = cloud ? targ : pred;
    float x = src[3 * rem], y = src[3 * rem + 1], z = src[3 * rem + 2];
    int cx = cell_coord(x), cy = cell_coord(y), cz = cell_coord(z);
    int b = rem / NPTS;
    atomicAdd(&g_cnt[cloud][b][(cz * GRIDD + cy) * GRIDD + cx], 1u);
}

// ---- exclusive prefix sum over 32768 cells per (cloud,batch); pack start|cnt<<16 ----
__global__ void scan_kernel() {
    int inst = blockIdx.x;               // 0..15
    int cloud = inst >> 3, b = inst & 7;
    const unsigned* cnt = g_cnt[cloud][b];
    unsigned* cs = g_cs[cloud][b];
    int t = threadIdx.x;                 // 1024 threads, 32 cells each
    int base = t * 32;
    unsigned local[32], s = 0;
#pragma unroll
    for (int i = 0; i < 32; i++) { local[i] = s; s += cnt[base + i]; }
    __shared__ unsigned sh[1024];
    sh[t] = s;
    __syncthreads();
    for (int o = 1; o < 1024; o <<= 1) {
        unsigned v = (t >= o) ? sh[t - o] : 0u;
        __syncthreads();
        sh[t] += v;
        __syncthreads();
    }
    unsigned off = sh[t] - s;            // exclusive offset for this thread's span
#pragma unroll
    for (int i = 0; i < 32; i++)
        cs[base + i] = (off + local[i]) | (cnt[base + i] << 16);
}

// ---- scatter points into cell-sorted order ----
__global__ void scatter_kernel(const float* __restrict__ pred, const float* __restrict__ targ) {
    int i = blockIdx.x * blockDim.x + threadIdx.x;
    if (i >= 2 * BB * NPTS) return;
    int cloud = i / (BB * NPTS);
    int rem = i - cloud * (BB * NPTS);
    const float* src = cloud ? targ : pred;
    float x = src[3 * rem], y = src[3 * rem + 1], z = src[3 * rem + 2];
    int cx = cell_coord(x), cy = cell_coord(y), cz = cell_coord(z);
    int b = rem / NPTS;
    int cc = (cz * GRIDD + cy) * GRIDD + cx;
    unsigned pos = (g_cs[cloud][b][cc] & 0xFFFFu) + atomicAdd(&g_fill[cloud][b][cc], 1u);
    g_sorted[cloud][b][pos] = make_float4(x, y, z, 0.0f);
}

// ---- exact NN via expanding Chebyshev rings ----
// After scanning all cells with cheb <= r, every unscanned point lies >= r*S
// from the query (cells separate intervals by >= (m-1)*S; clamped outliers are
// strictly farther than their assigned cell implies -> bound stays valid).
__global__ void __launch_bounds__(256) query_kernel() {
    const int dir = blockIdx.z, b = blockIdx.y;
    const int qidx = blockIdx.x * 256 + threadIdx.x;

    const float4 q = g_sorted[dir][b][qidx];
    const float4*   __restrict__ pts = g_sorted[1 - dir][b];
    const unsigned* __restrict__ cs  = g_cs[1 - dir][b];

    const int cx = cell_coord(q.x), cy = cell_coord(q.y), cz = cell_coord(q.z);
    float best = INFINITY;

#define SCAN_CELL(X, Y, Z)                                                \
    do {                                                                  \
        unsigned v_ = cs[((Z) * GRIDD + (Y)) * GRIDD + (X)];              \
        unsigned s0_ = v_ & 0xFFFFu, n_ = v_ >> 16;                       \
        for (unsigned i_ = 0; i_ < n_; i_++) {                            \
            float4 p_ = pts[s0_ + i_];                                    \
            float dx_ = q.x - p_.x, dy_ = q.y - p_.y, dz_ = q.z - p_.z;   \
            float d_ = fmaf(dx_, dx_, fmaf(dy_, dy_, dz_ * dz_));         \
            best = fminf(best, d_);                                       \
        }                                                                 \
    } while (0)

    SCAN_CELL(cx, cy, cz);  // ring 0

    for (int r = 1; r < GRIDD; r++) {
        float bnd = (float)(r - 1) * S_CELL * 0.9995f;  // safe lower bound after ring r-1
        if (best <= bnd * bnd) break;
        for (int dz = -r; dz <= r; dz++) {
            int Z = cz + dz;
            if ((unsigned)Z >= GRIDD) continue;
            int mz = abs(dz);
            for (int dy = -r; dy <= r; dy++) {
                int Y = cy + dy;
                if ((unsigned)Y >= GRIDD) continue;
                if (max(mz, abs(dy)) == r) {
                    for (int dx = -r; dx <= r; dx++) {
                        int X = cx + dx;
                        if ((unsigned)X >= GRIDD) continue;
                        SCAN_CELL(X, Y, Z);
                    }
                } else {
                    int X = cx - r;
                    if (X >= 0) SCAN_CELL(X, cy + dy, Z);
                    X = cx + r;
                    if (X < GRIDD) SCAN_CELL(X, cy + dy, Z);
                }
            }
        }
    }
#undef SCAN_CELL

    // block-sum the NN distances, one double atomic per block
    float s = best;
#pragma unroll
    for (int o = 16; o; o >>= 1) s += __shfl_down_sync(0xFFFFFFFFu, s, o);
    __shared__ float sh[8];
    if ((threadIdx.x & 31) == 0) sh[threadIdx.x >> 5] = s;
    __syncthreads();
    if (threadIdx.x == 0) {
        float t = 0.f;
#pragma unroll
        for (int i = 0; i < 8; i++) t += sh[i];
        atomicAdd(&g_loss[dir], (double)t);
    }
}

// ---- final: loss = mean(dist1) + mean(dist2) ----
__global__ void final_kernel(float* __restrict__ out) {
    out[0] = (float)((g_loss[0] + g_loss[1]) * (1.0 / (double)(BB * NPTS)));
}

extern "C" void kernel_launch(void* const* d_in, const int* in_sizes, int n_in,
                              void* d_out, int out_size) {
    const float* pred = (const float*)d_in[0];
    const float* targ = (const float*)d_in[1];
    zero_kernel<<<(2 * BB * CELLS + 255) / 256, 256>>>();
    hist_kernel<<<(2 * BB * NPTS + 255) / 256, 256>>>(pred, targ);
    scan_kernel<<<16, 1024>>>();
    scatter_kernel<<<(2 * BB * NPTS + 255) / 256, 256>>>(pred, targ);
    query_kernel<<<dim3(NPTS / 256, BB, 2), 256>>>();
    final_kernel<<<1, 1>>>((float*)d_out);
}

// round 11
// speedup vs baseline: 1.1566x; 1.1566x over previous
#include <cuda_runtime.h>
#include <cstdint>

#define BB     8
#define NPTS   8192
#define GRIDD  32
#define CELLS  (GRIDD * GRIDD * GRIDD)
#define RANGE_LO (-6.5f)
#define S_CELL   0.40625f          // 13.0 / 32
#define INV_S    (1.0f / S_CELL)

// ---- scratch (no allocations allowed) ----
__device__ float4   g_sorted[2][BB][NPTS];   // cell-sorted points (x,y,z,0)
__device__ unsigned g_cnt[2][BB][CELLS];     // per-cell counts
__device__ unsigned g_cs[2][BB][CELLS];      // packed: start | (cnt << 16)
__device__ unsigned g_fill[2][BB][CELLS];    // scatter cursors
__device__ double   g_loss[2];

__device__ __forceinline__ int cell_coord(float v) {
    int c = (int)floorf((v - RANGE_LO) * INV_S);
    return min(max(c, 0), GRIDD - 1);
}

// ---- zero counters/cursors/accumulators ----
__global__ void zero_kernel() {
    int i = blockIdx.x * blockDim.x + threadIdx.x;
    if (i < 2 * BB * CELLS) {
        ((unsigned*)g_cnt)[i] = 0u;
        ((unsigned*)g_fill)[i] = 0u;
    }
    if (i < 2) g_loss[i] = 0.0;
}

// ---- histogram: count points per cell ----
__global__ void hist_kernel(const float* __restrict__ pred, const float* __restrict__ targ) {
    int i = blockIdx.x * blockDim.x + threadIdx.x;
    if (i >= 2 * BB * NPTS) return;
    int cloud = i / (BB * NPTS);
    int rem = i - cloud * (BB * NPTS);
    const float* src = cloud ? targ : pred;
    float x = src[3 * rem], y = src[3 * rem + 1], z = src[3 * rem + 2];
    int cx = cell_coord(x), cy = cell_coord(y), cz = cell_coord(z);
    int b = rem / NPTS;
    atomicAdd(&g_cnt[cloud][b][(cz * GRIDD + cy) * GRIDD + cx], 1u);
}

// ---- exclusive prefix sum over 32768 cells per (cloud,batch); pack start|cnt<<16 ----
__global__ void scan_kernel() {
    int inst = blockIdx.x;               // 0..15
    int cloud = inst >> 3, b = inst & 7;
    const unsigned* cnt = g_cnt[cloud][b];
    unsigned* cs = g_cs[cloud][b];
    int t = threadIdx.x;                 // 1024 threads, 32 cells each
    int base = t * 32;
    unsigned local[32], s = 0;
#pragma unroll
    for (int i = 0; i < 32; i++) { local[i] = s; s += cnt[base + i]; }
    __shared__ unsigned sh[1024];
    sh[t] = s;
    __syncthreads();
    for (int o = 1; o < 1024; o <<= 1) {
        unsigned v = (t >= o) ? sh[t - o] : 0u;
        __syncthreads();
        sh[t] += v;
        __syncthreads();
    }
    unsigned off = sh[t] - s;            // exclusive offset for this thread's span
#pragma unroll
    for (int i = 0; i < 32; i++)
        cs[base + i] = (off + local[i]) | (cnt[base + i] << 16);
}

// ---- scatter points into cell-sorted order ----
__global__ void scatter_kernel(const float* __restrict__ pred, const float* __restrict__ targ) {
    int i = blockIdx.x * blockDim.x + threadIdx.x;
    if (i >= 2 * BB * NPTS) return;
    int cloud = i / (BB * NPTS);
    int rem = i - cloud * (BB * NPTS);
    const float* src = cloud ? targ : pred;
    float x = src[3 * rem], y = src[3 * rem + 1], z = src[3 * rem + 2];
    int cx = cell_coord(x), cy = cell_coord(y), cz = cell_coord(z);
    int b = rem / NPTS;
    int cc = (cz * GRIDD + cy) * GRIDD + cx;
    unsigned pos = (g_cs[cloud][b][cc] & 0xFFFFu) + atomicAdd(&g_fill[cloud][b][cc], 1u);
    g_sorted[cloud][b][pos] = make_float4(x, y, z, 0.0f);
}

// ---- exact NN: expanding Chebyshev rings + per-cell box-distance pruning ----
// Ring bound: once all cells with cheb <= r-1 are scanned, any unscanned point
// differs by >= (r-1)*S in some axis. Box prune: a cell can only beat `best`
// if the query's distance-squared to that cell's box is < best. Both bounds
// carry safety factors so fp rounding can only cause EXTRA scanning.
__global__ void __launch_bounds__(256) query_kernel() {
    const int dir = blockIdx.z, b = blockIdx.y;
    const int qidx = blockIdx.x * 256 + threadIdx.x;

    const float4 q = g_sorted[dir][b][qidx];
    const float4*   __restrict__ pts = g_sorted[1 - dir][b];
    const unsigned* __restrict__ cs  = g_cs[1 - dir][b];

    const int cx = cell_coord(q.x), cy = cell_coord(q.y), cz = cell_coord(q.z);
    float best0 = INFINITY, best1 = INFINITY;   // two accumulators break fmin chain

#define SCAN_CELL(X, Y, Z)                                                    \
    do {                                                                      \
        unsigned v_ = cs[((Z) * GRIDD + (Y)) * GRIDD + (X)];                  \
        unsigned s0_ = v_ & 0xFFFFu, n_ = v_ >> 16;                           \
        unsigned i_ = 0;                                                      \
        for (; i_ + 2 <= n_; i_ += 2) {                                       \
            float4 p0_ = pts[s0_ + i_];                                       \
            float4 p1_ = pts[s0_ + i_ + 1];                                   \
            float dx0_ = q.x - p0_.x, dy0_ = q.y - p0_.y, dz0_ = q.z - p0_.z; \
            float dx1_ = q.x - p1_.x, dy1_ = q.y - p1_.y, dz1_ = q.z - p1_.z; \
            best0 = fminf(best0, fmaf(dx0_, dx0_, fmaf(dy0_, dy0_, dz0_ * dz0_))); \
            best1 = fminf(best1, fmaf(dx1_, dx1_, fmaf(dy1_, dy1_, dz1_ * dz1_))); \
        }                                                                     \
        if (i_ < n_) {                                                        \
            float4 p0_ = pts[s0_ + i_];                                       \
            float dx0_ = q.x - p0_.x, dy0_ = q.y - p0_.y, dz0_ = q.z - p0_.z; \
            best0 = fminf(best0, fmaf(dx0_, dx0_, fmaf(dy0_, dy0_, dz0_ * dz0_))); \
        }                                                                     \
    } while (0)

    SCAN_CELL(cx, cy, cz);  // ring 0 (own cell)

    // distances from q to its own cell's faces (all >= 0)
    const float fxm = q.x - (RANGE_LO + cx * S_CELL), fxp = (RANGE_LO + (cx + 1) * S_CELL) - q.x;
    const float fym = q.y - (RANGE_LO + cy * S_CELL), fyp = (RANGE_LO + (cy + 1) * S_CELL) - q.y;
    const float fzm = q.z - (RANGE_LO + cz * S_CELL), fzp = (RANGE_LO + (cz + 1) * S_CELL) - q.z;

    for (int r = 1; r < GRIDD; r++) {
        float best = fminf(best0, best1);
        float bnd = (float)(r - 1) * S_CELL * 0.9995f;
        if (best <= bnd * bnd) break;
        float bcut = best * 1.0005f;   // prune threshold with slack (errs toward scanning)
        for (int dz = -r; dz <= r; dz++) {
            int Z = cz + dz;
            if ((unsigned)Z >= GRIDD) continue;
            float az = (dz == 0) ? 0.0f
                     : fmaf((float)(abs(dz) - 1), S_CELL, (dz > 0) ? fzp : fzm);
            float az2 = az * az;
            if (az2 >= bcut) continue;
            int edge_z = (abs(dz) == r);
            for (int dy = -r; dy <= r; dy++) {
                int Y = cy + dy;
                if ((unsigned)Y >= GRIDD) continue;
                float ay = (dy == 0) ? 0.0f
                         : fmaf((float)(abs(dy) - 1), S_CELL, (dy > 0) ? fyp : fym);
                float ayz2 = fmaf(ay, ay, az2);
                if (ayz2 >= bcut) continue;
                if (edge_z || abs(dy) == r) {
                    for (int dx = -r; dx <= r; dx++) {
                        int X = cx + dx;
                        if ((unsigned)X >= GRIDD) continue;
                        float ax = (dx == 0) ? 0.0f
                                 : fmaf((float)(abs(dx) - 1), S_CELL, (dx > 0) ? fxp : fxm);
                        if (fmaf(ax, ax, ayz2) < bcut) SCAN_CELL(X, Y, Z);
                    }
                } else {  // interior (dy,dz): only dx = +/- r on this shell
                    int X = cx - r;
                    float ax = fmaf((float)(r - 1), S_CELL, fxm);
                    if (X >= 0 && fmaf(ax, ax, ayz2) < bcut) SCAN_CELL(X, Y, Z);
                    X = cx + r;
                    ax = fmaf((float)(r - 1), S_CELL, fxp);
                    if (X < GRIDD && fmaf(ax, ax, ayz2) < bcut) SCAN_CELL(X, Y, Z);
                }
            }
        }
    }
#undef SCAN_CELL

    // block-sum the NN distances, one double atomic per block
    float s = fminf(best0, best1);
#pragma unroll
    for (int o = 16; o; o >>= 1) s += __shfl_down_sync(0xFFFFFFFFu, s, o);
    __shared__ float sh[8];
    if ((threadIdx.x & 31) == 0) sh[threadIdx.x >> 5] = s;
    __syncthreads();
    if (threadIdx.x == 0) {
        float t = 0.f;
#pragma unroll
        for (int i = 0; i < 8; i++) t += sh[i];
        atomicAdd(&g_loss[dir], (double)t);
    }
}

// ---- final: loss = mean(dist1) + mean(dist2) ----
__global__ void final_kernel(float* __restrict__ out) {
    out[0] = (float)((g_loss[0] + g_loss[1]) * (1.0 / (double)(BB * NPTS)));
}

extern "C" void kernel_launch(void* const* d_in, const int* in_sizes, int n_in,
                              void* d_out, int out_size) {
    const float* pred = (const float*)d_in[0];
    const float* targ = (const float*)d_in[1];
    zero_kernel<<<(2 * BB * CELLS + 255) / 256, 256>>>();
    hist_kernel<<<(2 * BB * NPTS + 255) / 256, 256>>>(pred, targ);
    scan_kernel<<<16, 1024>>>();
    scatter_kernel<<<(2 * BB * NPTS + 255) / 256, 256>>>(pred, targ);
    query_kernel<<<dim3(NPTS / 256, BB, 2), 256>>>();
    final_kernel<<<1, 1>>>((float*)d_out);
}

// round 12
// speedup vs baseline: 1.1867x; 1.0260x over previous
#include <cuda_runtime.h>
#include <cstdint>

#define BB     8
#define NPTS   8192
#define GRIDD  32
#define CELLS  (GRIDD * GRIDD * GRIDD)
#define RANGE_LO (-6.5f)
#define S_CELL   0.40625f          // 13.0 / 32
#define INV_S    (1.0f / S_CELL)
#define NSLOTS   64                // partial-sum slots per direction

// ---- scratch (no allocations allowed) ----
__device__ float4   g_sorted[2][BB][NPTS];   // cell-sorted points (x,y,z,|p|^2)
__device__ unsigned g_cnt[2][BB][CELLS];     // per-cell counts
__device__ unsigned g_cs[2][BB][CELLS];      // packed: start | (cnt << 16)
__device__ unsigned g_fill[2][BB][CELLS];    // scatter cursors
__device__ double   g_part[2][NSLOTS];       // spread partial sums

__device__ __forceinline__ int cell_coord(float v) {
    int c = (int)floorf((v - RANGE_LO) * INV_S);
    return min(max(c, 0), GRIDD - 1);
}

// ---- zero counters/cursors/accumulators ----
__global__ void zero_kernel() {
    int i = blockIdx.x * blockDim.x + threadIdx.x;
    if (i < 2 * BB * CELLS) {
        ((unsigned*)g_cnt)[i] = 0u;
        ((unsigned*)g_fill)[i] = 0u;
    }
    if (i < 2 * NSLOTS) ((double*)g_part)[i] = 0.0;
}

// ---- histogram: count points per cell ----
__global__ void hist_kernel(const float* __restrict__ pred, const float* __restrict__ targ) {
    int i = blockIdx.x * blockDim.x + threadIdx.x;
    if (i >= 2 * BB * NPTS) return;
    int cloud = i / (BB * NPTS);
    int rem = i - cloud * (BB * NPTS);
    const float* src = cloud ? targ : pred;
    float x = src[3 * rem], y = src[3 * rem + 1], z = src[3 * rem + 2];
    int cx = cell_coord(x), cy = cell_coord(y), cz = cell_coord(z);
    int b = rem / NPTS;
    atomicAdd(&g_cnt[cloud][b][(cz * GRIDD + cy) * GRIDD + cx], 1u);
}

// ---- exclusive prefix sum over 32768 cells per (cloud,batch); pack start|cnt<<16 ----
__global__ void scan_kernel() {
    int inst = blockIdx.x;               // 0..15
    int cloud = inst >> 3, b = inst & 7;
    const unsigned* cnt = g_cnt[cloud][b];
    unsigned* cs = g_cs[cloud][b];
    int t = threadIdx.x;                 // 1024 threads, 32 cells each
    int base = t * 32;
    unsigned local[32], s = 0;
#pragma unroll
    for (int i = 0; i < 32; i++) { local[i] = s; s += cnt[base + i]; }
    __shared__ unsigned sh[1024];
    sh[t] = s;
    __syncthreads();
    for (int o = 1; o < 1024; o <<= 1) {
        unsigned v = (t >= o) ? sh[t - o] : 0u;
        __syncthreads();
        sh[t] += v;
        __syncthreads();
    }
    unsigned off = sh[t] - s;            // exclusive offset for this thread's span
#pragma unroll
    for (int i = 0; i < 32; i++)
        cs[base + i] = (off + local[i]) | (cnt[base + i] << 16);
}

// ---- scatter points into cell-sorted order (store |p|^2 in w) ----
__global__ void scatter_kernel(const float* __restrict__ pred, const float* __restrict__ targ) {
    int i = blockIdx.x * blockDim.x + threadIdx.x;
    if (i >= 2 * BB * NPTS) return;
    int cloud = i / (BB * NPTS);
    int rem = i - cloud * (BB * NPTS);
    const float* src = cloud ? targ : pred;
    float x = src[3 * rem], y = src[3 * rem + 1], z = src[3 * rem + 2];
    int cx = cell_coord(x), cy = cell_coord(y), cz = cell_coord(z);
    int b = rem / NPTS;
    int cc = (cz * GRIDD + cy) * GRIDD + cx;
    unsigned pos = (g_cs[cloud][b][cc] & 0xFFFFu) + atomicAdd(&g_fill[cloud][b][cc], 1u);
    g_sorted[cloud][b][pos] = make_float4(x, y, z, x * x + y * y + z * z);
}

// ---- warp-cooperative exact NN ----
// One warp per (cloud, batch, query cell). All control flow is warp-uniform:
// lanes hold different query points of the SAME cell, so the neighbor-box
// traversal is identical across lanes (zero divergence). The (z,y,x)-ordered
// sort makes each 3-cell x-row CONTIGUOUS in the sorted array -> the 27-cell
// neighborhood is 9 contiguous scans. Candidates are broadcast loads.
// Exact bound: after scanning box [x0..x1]x[y0..y1]x[z0..z1], any unscanned
// point is at least dist(q, box boundary) away (faces at grid edge have no
// cells beyond -> excluded; clamped outliers lie even farther out, so cell-
// implied bounds remain valid lower bounds). Expand shells until all lanes
// satisfy best <= (0.999*bnd)^2; when the box covers the grid, bnd = INF.
__global__ void __launch_bounds__(256) query_kernel() {
    int wg = blockIdx.x * 8 + (threadIdx.x >> 5);
    int lane = threadIdx.x & 31;
    int cloud = wg >> 18;
    int b = (wg >> 15) & 7;
    int cell = wg & (CELLS - 1);

    unsigned qv = g_cs[cloud][b][cell];
    unsigned nq = qv >> 16;
    if (nq == 0) return;                 // warp-uniform exit
    unsigned qs = qv & 0xFFFFu;
    int cx = cell & 31, cy = (cell >> 5) & 31, cz = cell >> 10;

    const float4*   __restrict__ Pq  = g_sorted[cloud][b];
    const float4*   __restrict__ Pc  = g_sorted[cloud ^ 1][b];
    const unsigned* __restrict__ csc = g_cs[cloud ^ 1][b];

    float acc = 0.f;

    for (unsigned q0 = 0; q0 < nq; q0 += 32) {
        unsigned qi = q0 + lane;
        bool active = qi < nq;
        float4 q = Pq[qs + (active ? qi : 0u)];
        float m2x = -2.f * q.x, m2y = -2.f * q.y, m2z = -2.f * q.z, qw = q.w;
        float best = INFINITY;

#define SCAN_ROW(XA, XB, Y, Z) do {                                              \
        int base_ = ((Z) * GRIDD + (Y)) * GRIDD;                                 \
        unsigned va_ = csc[base_ + (XA)];                                        \
        unsigned vb_ = csc[base_ + (XB)];                                        \
        unsigned i_ = va_ & 0xFFFFu;                                             \
        unsigned e_ = (vb_ & 0xFFFFu) + (vb_ >> 16);                             \
        for (; i_ + 2 <= e_; i_ += 2) {                                          \
            float4 p0_ = Pc[i_], p1_ = Pc[i_ + 1];                               \
            float d0_ = fmaf(m2x, p0_.x, fmaf(m2y, p0_.y, fmaf(m2z, p0_.z, qw + p0_.w))); \
            float d1_ = fmaf(m2x, p1_.x, fmaf(m2y, p1_.y, fmaf(m2z, p1_.z, qw + p1_.w))); \
            best = fminf(best, fminf(d0_, d1_));                                 \
        }                                                                        \
        if (i_ < e_) {                                                           \
            float4 p0_ = Pc[i_];                                                 \
            best = fminf(best, fmaf(m2x, p0_.x, fmaf(m2y, p0_.y, fmaf(m2z, p0_.z, qw + p0_.w)))); \
        }                                                                        \
    } while (0)

        int x0 = max(cx - 1, 0), x1 = min(cx + 1, GRIDD - 1);
        int y0 = max(cy - 1, 0), y1 = min(cy + 1, GRIDD - 1);
        int z0 = max(cz - 1, 0), z1 = min(cz + 1, GRIDD - 1);
        for (int Z = z0; Z <= z1; Z++)
            for (int Y = y0; Y <= y1; Y++)
                SCAN_ROW(x0, x1, Y, Z);

        int r = 1;
        while (true) {
            float bnd = INFINITY;
            if (x0 > 0)         bnd = fminf(bnd, q.x - (RANGE_LO + x0 * S_CELL));
            if (x1 < GRIDD - 1) bnd = fminf(bnd, (RANGE_LO + (x1 + 1) * S_CELL) - q.x);
            if (y0 > 0)         bnd = fminf(bnd, q.y - (RANGE_LO + y0 * S_CELL));
            if (y1 < GRIDD - 1) bnd = fminf(bnd, (RANGE_LO + (y1 + 1) * S_CELL) - q.y);
            if (z0 > 0)         bnd = fminf(bnd, q.z - (RANGE_LO + z0 * S_CELL));
            if (z1 < GRIDD - 1) bnd = fminf(bnd, (RANGE_LO + (z1 + 1) * S_CELL) - q.z);
            bnd *= 0.999f;                       // rounding slack: errs toward extra scans
            bool ok = !active || (best <= bnd * bnd);
            if (__all_sync(0xFFFFFFFFu, ok)) break;
            r++;
            int nx0 = max(cx - r, 0), nx1 = min(cx + r, GRIDD - 1);
            int ny0 = max(cy - r, 0), ny1 = min(cy + r, GRIDD - 1);
            int nz0 = max(cz - r, 0), nz1 = min(cz + r, GRIDD - 1);
            for (int Z = nz0; Z <= nz1; Z++)
                for (int Y = ny0; Y <= ny1; Y++) {
                    if (Z < z0 || Z > z1 || Y < y0 || Y > y1) {
                        SCAN_ROW(nx0, nx1, Y, Z);
                    } else {
                        if (nx0 < x0) SCAN_ROW(nx0, x0 - 1, Y, Z);
                        if (nx1 > x1) SCAN_ROW(x1 + 1, nx1, Y, Z);
                    }
                }
            x0 = nx0; x1 = nx1; y0 = ny0; y1 = ny1; z0 = nz0; z1 = nz1;
        }
#undef SCAN_ROW

        if (active) acc += best;
    }

    // warp-reduce and push one double atomic to a spread slot
#pragma unroll
    for (int o = 16; o; o >>= 1) acc += __shfl_down_sync(0xFFFFFFFFu, acc, o);
    if (lane == 0)
        atomicAdd(&g_part[cloud][cell & (NSLOTS - 1)], (double)acc);
}

// ---- final: loss = mean(dist1) + mean(dist2) ----
__global__ void final_kernel(float* __restrict__ out) {
    double s = 0.0;
    for (int i = 0; i < 2 * NSLOTS; i++) s += ((const double*)g_part)[i];
    out[0] = (float)(s * (1.0 / (double)(BB * NPTS)));
}

extern "C" void kernel_launch(void* const* d_in, const int* in_sizes, int n_in,
                              void* d_out, int out_size) {
    const float* pred = (const float*)d_in[0];
    const float* targ = (const float*)d_in[1];
    zero_kernel<<<(2 * BB * CELLS + 255) / 256, 256>>>();
    hist_kernel<<<(2 * BB * NPTS + 255) / 256, 256>>>(pred, targ);
    scan_kernel<<<16, 1024>>>();
    scatter_kernel<<<(2 * BB * NPTS + 255) / 256, 256>>>(pred, targ);
    query_kernel<<<2 * BB * CELLS / 8, 256>>>();
    final_kernel<<<1, 1>>>((float*)d_out);
}

// round 13
// speedup vs baseline: 1.3681x; 1.1529x over previous
#include <cuda_runtime.h>
#include <cstdint>

#define BB     8
#define NPTS   8192
#define GRIDD  32
#define CELLS  (GRIDD * GRIDD * GRIDD)
#define RANGE_LO (-6.5f)
#define S_CELL   0.40625f          // 13.0 / 32
#define INV_S    (1.0f / S_CELL)
#define NSLOTS   64                // partial-sum slots per direction

// ---- scratch (no allocations allowed) ----
__device__ float4   g_sorted[2][BB][NPTS];   // cell-sorted points (x,y,z,|p|^2)
__device__ unsigned g_cnt[2][BB][CELLS];     // per-cell counts
__device__ unsigned g_cs[2][BB][CELLS];      // packed: start | (cnt << 16)
__device__ unsigned g_fill[2][BB][CELLS];    // scatter cursors
__device__ double   g_part[2][NSLOTS];       // spread partial sums

__device__ __forceinline__ int cell_coord(float v) {
    int c = (int)floorf((v - RANGE_LO) * INV_S);
    return min(max(c, 0), GRIDD - 1);
}

// ---- zero counters/cursors/accumulators ----
__global__ void zero_kernel() {
    int i = blockIdx.x * blockDim.x + threadIdx.x;
    if (i < 2 * BB * CELLS) {
        ((unsigned*)g_cnt)[i] = 0u;
        ((unsigned*)g_fill)[i] = 0u;
    }
    if (i < 2 * NSLOTS) ((double*)g_part)[i] = 0.0;
}

// ---- histogram: count points per cell ----
__global__ void hist_kernel(const float* __restrict__ pred, const float* __restrict__ targ) {
    int i = blockIdx.x * blockDim.x + threadIdx.x;
    if (i >= 2 * BB * NPTS) return;
    int cloud = i / (BB * NPTS);
    int rem = i - cloud * (BB * NPTS);
    const float* src = cloud ? targ : pred;
    float x = src[3 * rem], y = src[3 * rem + 1], z = src[3 * rem + 2];
    int cx = cell_coord(x), cy = cell_coord(y), cz = cell_coord(z);
    int b = rem / NPTS;
    atomicAdd(&g_cnt[cloud][b][(cz * GRIDD + cy) * GRIDD + cx], 1u);
}

// ---- exclusive prefix sum over 32768 cells per (cloud,batch); pack start|cnt<<16 ----
__global__ void scan_kernel() {
    int inst = blockIdx.x;               // 0..15
    int cloud = inst >> 3, b = inst & 7;
    const unsigned* cnt = g_cnt[cloud][b];
    unsigned* cs = g_cs[cloud][b];
    int t = threadIdx.x;                 // 1024 threads, 32 cells each
    int base = t * 32;
    unsigned local[32], s = 0;
#pragma unroll
    for (int i = 0; i < 32; i++) { local[i] = s; s += cnt[base + i]; }
    __shared__ unsigned sh[1024];
    sh[t] = s;
    __syncthreads();
    for (int o = 1; o < 1024; o <<= 1) {
        unsigned v = (t >= o) ? sh[t - o] : 0u;
        __syncthreads();
        sh[t] += v;
        __syncthreads();
    }
    unsigned off = sh[t] - s;            // exclusive offset for this thread's span
#pragma unroll
    for (int i = 0; i < 32; i++)
        cs[base + i] = (off + local[i]) | (cnt[base + i] << 16);
}

// ---- scatter points into cell-sorted order (store |p|^2 in w) ----
__global__ void scatter_kernel(const float* __restrict__ pred, const float* __restrict__ targ) {
    int i = blockIdx.x * blockDim.x + threadIdx.x;
    if (i >= 2 * BB * NPTS) return;
    int cloud = i / (BB * NPTS);
    int rem = i - cloud * (BB * NPTS);
    const float* src = cloud ? targ : pred;
    float x = src[3 * rem], y = src[3 * rem + 1], z = src[3 * rem + 2];
    int cx = cell_coord(x), cy = cell_coord(y), cz = cell_coord(z);
    int b = rem / NPTS;
    int cc = (cz * GRIDD + cy) * GRIDD + cx;
    unsigned pos = (g_cs[cloud][b][cc] & 0xFFFFu) + atomicAdd(&g_fill[cloud][b][cc], 1u);
    g_sorted[cloud][b][pos] = make_float4(x, y, z, x * x + y * y + z * z);
}

// ---- warp-cooperative exact NN over MERGED 4-cell x-groups ----
// One warp per (cloud, batch, cz, cy, cx-group-of-4). The 4 cells' query
// points are CONTIGUOUS in the sorted array (x is the fastest sort key), so
// the warp processes them in full 32-lane batches (lane = query). The merged
// neighborhood box is x:[cx0-1, cx0+4] x y,z: +/-1 -> 9 contiguous row scans;
// candidates stream as warp-uniform broadcast loads, 6 issue slots per
// candidate serving 32 query-evals. Exact bound: after scanning the box, any
// unscanned point is >= dist(q, box boundary) away (range +-6.5 >> max|coord|
// means every point lies strictly inside its cell box). Expand the box by 1
// each round (rescanning only new rows) until all lanes' best <= bound^2.
__global__ void __launch_bounds__(256) query_kernel() {
    int wg = blockIdx.x * 8 + (threadIdx.x >> 5);
    int lane = threadIdx.x & 31;
    int cx0 = (wg & 7) * 4;
    int cy = (wg >> 3) & 31;
    int cz = (wg >> 8) & 31;
    int b  = (wg >> 13) & 7;
    int cloud = (wg >> 16) & 1;

    const unsigned* __restrict__ csq = g_cs[cloud][b];
    unsigned va = csq[(cz * GRIDD + cy) * GRIDD + cx0];
    unsigned vb = csq[(cz * GRIDD + cy) * GRIDD + cx0 + 3];
    unsigned qs = va & 0xFFFFu;
    unsigned qe = (vb & 0xFFFFu) + (vb >> 16);
    if (qs >= qe) return;                // warp-uniform exit (empty region)

    const float4*   __restrict__ Pq  = g_sorted[cloud][b];
    const float4*   __restrict__ Pc  = g_sorted[cloud ^ 1][b];
    const unsigned* __restrict__ csc = g_cs[cloud ^ 1][b];

    float acc = 0.f;

#define SCAN_ROW(XA, XB, Y, Z) do {                                              \
        int base_ = ((Z) * GRIDD + (Y)) * GRIDD;                                 \
        unsigned va_ = csc[base_ + (XA)];                                        \
        unsigned vb_ = csc[base_ + (XB)];                                        \
        unsigned i_ = va_ & 0xFFFFu;                                             \
        unsigned e_ = (vb_ & 0xFFFFu) + (vb_ >> 16);                             \
        for (; i_ + 2 <= e_; i_ += 2) {                                          \
            float4 p0_ = Pc[i_], p1_ = Pc[i_ + 1];                               \
            float d0_ = fmaf(m2x, p0_.x, fmaf(m2y, p0_.y, fmaf(m2z, p0_.z, qw + p0_.w))); \
            float d1_ = fmaf(m2x, p1_.x, fmaf(m2y, p1_.y, fmaf(m2z, p1_.z, qw + p1_.w))); \
            best = fminf(best, fminf(d0_, d1_));                                 \
        }                                                                        \
        if (i_ < e_) {                                                           \
            float4 p0_ = Pc[i_];                                                 \
            best = fminf(best, fmaf(m2x, p0_.x, fmaf(m2y, p0_.y, fmaf(m2z, p0_.z, qw + p0_.w)))); \
        }                                                                        \
    } while (0)

    for (unsigned q0 = qs; q0 < qe; q0 += 32) {
        unsigned qi = q0 + lane;
        bool active = qi < qe;
        float4 q = Pq[active ? qi : qe - 1];
        float m2x = -2.f * q.x, m2y = -2.f * q.y, m2z = -2.f * q.z, qw = q.w;
        float best = INFINITY;

        int x0 = max(cx0 - 1, 0), x1 = min(cx0 + 4, GRIDD - 1);
        int y0 = max(cy - 1, 0),  y1 = min(cy + 1, GRIDD - 1);
        int z0 = max(cz - 1, 0),  z1 = min(cz + 1, GRIDD - 1);
        for (int Z = z0; Z <= z1; Z++)
            for (int Y = y0; Y <= y1; Y++)
                SCAN_ROW(x0, x1, Y, Z);

        while (true) {
            float bnd = INFINITY;
            if (x0 > 0)         bnd = fminf(bnd, q.x - (RANGE_LO + x0 * S_CELL));
            if (x1 < GRIDD - 1) bnd = fminf(bnd, (RANGE_LO + (x1 + 1) * S_CELL) - q.x);
            if (y0 > 0)         bnd = fminf(bnd, q.y - (RANGE_LO + y0 * S_CELL));
            if (y1 < GRIDD - 1) bnd = fminf(bnd, (RANGE_LO + (y1 + 1) * S_CELL) - q.y);
            if (z0 > 0)         bnd = fminf(bnd, q.z - (RANGE_LO + z0 * S_CELL));
            if (z1 < GRIDD - 1) bnd = fminf(bnd, (RANGE_LO + (z1 + 1) * S_CELL) - q.z);
            bnd *= 0.999f;                       // rounding slack: errs toward extra scans
            bool ok = !active || (best <= bnd * bnd);
            if (__all_sync(0xFFFFFFFFu, ok)) break;
            int nx0 = max(x0 - 1, 0), nx1 = min(x1 + 1, GRIDD - 1);
            int ny0 = max(y0 - 1, 0), ny1 = min(y1 + 1, GRIDD - 1);
            int nz0 = max(z0 - 1, 0), nz1 = min(z1 + 1, GRIDD - 1);
            for (int Z = nz0; Z <= nz1; Z++)
                for (int Y = ny0; Y <= ny1; Y++) {
                    if (Z < z0 || Z > z1 || Y < y0 || Y > y1) {
                        SCAN_ROW(nx0, nx1, Y, Z);
                    } else {
                        if (nx0 < x0) SCAN_ROW(nx0, nx0, Y, Z);
                        if (nx1 > x1) SCAN_ROW(nx1, nx1, Y, Z);
                    }
                }
            x0 = nx0; x1 = nx1; y0 = ny0; y1 = ny1; z0 = nz0; z1 = nz1;
        }

        if (active) acc += best;
    }
#undef SCAN_ROW

    // warp-reduce and push one double atomic to a spread slot
#pragma unroll
    for (int o = 16; o; o >>= 1) acc += __shfl_down_sync(0xFFFFFFFFu, acc, o);
    if (lane == 0)
        atomicAdd(&g_part[cloud][wg & (NSLOTS - 1)], (double)acc);
}

// ---- final: loss = mean(dist1) + mean(dist2) ----
__global__ void final_kernel(float* __restrict__ out) {
    double s = 0.0;
    for (int i = 0; i < 2 * NSLOTS; i++) s += ((const double*)g_part)[i];
    out[0] = (float)(s * (1.0 / (double)(BB * NPTS)));
}

extern "C" void kernel_launch(void* const* d_in, const int* in_sizes, int n_in,
                              void* d_out, int out_size) {
    const float* pred = (const float*)d_in[0];
    const float* targ = (const float*)d_in[1];
    zero_kernel<<<(2 * BB * CELLS + 255) / 256, 256>>>();
    hist_kernel<<<(2 * BB * NPTS + 255) / 256, 256>>>(pred, targ);
    scan_kernel<<<16, 1024>>>();
    scatter_kernel<<<(2 * BB * NPTS + 255) / 256, 256>>>(pred, targ);
    query_kernel<<<(2 * BB * GRIDD * GRIDD * (GRIDD / 4)) / 8, 256>>>();
    final_kernel<<<1, 1>>>((float*)d_out);
}